// round 16
// baseline (speedup 1.0000x reference)
#include <cuda_runtime.h>
#include <cuda_fp16.h>
#include <math.h>
#include <cstdint>

#define NB 4
#define NN 256
#define OD 128

// ---------------- scratch (device globals; no allocation) ----------------
__device__ float g_f0a[NB * OD];
__device__ float g_f0b[NB * OD];
__device__ float g_f1a[NB * NN * OD];
__device__ float g_f1b[NB * NN * OD];
__device__ __half g_h2a[(size_t)NB * NN * NN * OD];
__device__ __half g_h2b[(size_t)NB * NN * NN * OD];
__device__ float g_r2A[NB * NN * 2 * OD];
__device__ float g_r2B[NB * NN * 2 * OD];
__device__ float g_Q[NB * NN * OD];
__device__ float g_P[NB * NN * OD];
__device__ __half g_Wt[OD * 2 * OD];

__device__ __forceinline__ float sigmoidf_(float x) {
    return 1.0f / (1.0f + __expf(-x));
}
__device__ __forceinline__ uint32_t smem_to_u32(const void* p) {
    uint32_t a;
    asm("{ .reg .u64 t; cvta.to.shared.u64 t, %1; cvt.u32.u64 %0, t; }" : "=r"(a) : "l"(p));
    return a;
}
__device__ __forceinline__ uint32_t pack_f16x2(float x, float y) {
    uint32_t r;
    asm("cvt.rn.f16x2.f32 %0, %2, %1;" : "=r"(r) : "f"(x), "f"(y));
    return r;
}
#define CP_ASYNC16(dst, src) \
    asm volatile("cp.async.cg.shared.global [%0], [%1], 16;" :: "r"(dst), "l"(src) : "memory")
#define CP_COMMIT() asm volatile("cp.async.commit_group;" ::: "memory")
#define CP_WAIT(n) asm volatile("cp.async.wait_group %0;" :: "n"(n) : "memory")

__device__ __forceinline__ void mma_f16(float* d, const uint32_t* a, const uint32_t* b) {
    asm volatile(
        "mma.sync.aligned.m16n8k16.row.col.f32.f16.f16.f32 "
        "{%0,%1,%2,%3}, {%4,%5,%6,%7}, {%8,%9}, {%0,%1,%2,%3};"
        : "+f"(d[0]), "+f"(d[1]), "+f"(d[2]), "+f"(d[3])
        : "r"(a[0]), "r"(a[1]), "r"(a[2]), "r"(a[3]), "r"(b[0]), "r"(b[1]));
}
__device__ __forceinline__ void ldm_x4(uint32_t& r0, uint32_t& r1, uint32_t& r2,
                                       uint32_t& r3, uint32_t addr) {
    asm volatile("ldmatrix.sync.aligned.m8n8.x4.shared.b16 {%0,%1,%2,%3}, [%4];"
                 : "=r"(r0), "=r"(r1), "=r"(r2), "=r"(r3) : "r"(addr));
}

// ---------------- fused prep: [reduce2] | qp(+r2next init) | wt | o0 --------
template <int D0, int D1, int D2, typename T2, bool DORED>
__global__ void k_prep(const float* __restrict__ f0, const float* __restrict__ f1,
                       const T2* __restrict__ f2, const float* __restrict__ W0,
                       const float* __restrict__ b0, const float* __restrict__ W2,
                       float* __restrict__ r2, float* __restrict__ Q,
                       float* __restrict__ P, __half* __restrict__ Wt,
                       float* __restrict__ o0, float* __restrict__ r2n) {
    constexpr int K = 2 * D2;
    constexpr int REDB = DORED ? 1024 : 0;
    int blk = blockIdx.x, t = threadIdx.x;
    __shared__ float s_qp[OD];
    __shared__ float s_o0[3 * OD];
    if (DORED && blk < REDB) {
        // ---- reduce2 on fp32 input tensor (layer 0 only)
        int i = blk & 255, b = blk >> 8;
        size_t rowbase = ((size_t)(b * NN + i)) * K;
        if (t < D2) {
            const float* base = (const float*)f2 + ((size_t)(b * NN + i)) * NN * D2 + t;
            float mx = -1e30f, mn = 1e30f;
#pragma unroll 8
            for (int j = 0; j < NN; j++) {
                float v = base[(size_t)j * D2];
                mx = fmaxf(mx, (j == i) ? 0.0f : v);
                mn = fminf(mn, (j == i) ? 1.0f : v);
            }
            r2[rowbase + t] = mx;
            r2[rowbase + D2 + t] = mn;
        }
    } else if (blk < REDB + 1024) {
        // ---- qp + r2next init
        int row = blk - REDB;
        if (r2n) {
            r2n[(size_t)row * 2 * OD + t] = 0.0f;
            r2n[(size_t)row * 2 * OD + OD + t] = 1.0f;
        }
        if (t < D1) s_qp[t] = f1[(size_t)row * D1 + t];
        __syncthreads();
        const float* Wa = W2;
        const float* Wc = W2 + (size_t)(D1 + D2) * OD;
        float aq = 0.0f, ap = 0.0f;
#pragma unroll 8
        for (int k = 0; k < D1; k++) {
            float v = s_qp[k];
            aq = fmaf(v, Wa[(size_t)k * OD + t], aq);
            ap = fmaf(v, Wc[(size_t)k * OD + t], ap);
        }
        Q[(size_t)row * OD + t] = aq;
        P[(size_t)row * OD + t] = ap;
    } else if (blk < REDB + 1024 + K) {
        int k = blk - (REDB + 1024);
        const float* src = (k < D2) ? W2 + (size_t)(D1 + k) * OD
                                    : W2 + (size_t)(2 * D1 + D2 + (k - D2)) * OD;
        Wt[(size_t)t * K + k] = __float2half_rn(src[t]);
    } else {
        int b = blk - (REDB + 1024 + K);
        if (t < D0) s_o0[t] = f0[b * D0 + t];
        if (t < D1) {
            float mx = -1e30f, mn = 1e30f;
            const float* base = f1 + (size_t)b * NN * D1 + t;
#pragma unroll 8
            for (int i2 = 0; i2 < NN; i2++) {
                float v = base[(size_t)i2 * D1];
                mx = fmaxf(mx, v);
                mn = fminf(mn, v);
            }
            s_o0[D0 + t] = mx;
            s_o0[D0 + D1 + t] = mn;
        }
        __syncthreads();
        constexpr int fan = D0 + 2 * D1;
        float acc = b0[t];
#pragma unroll 8
        for (int k = 0; k < fan; k++) acc = fmaf(s_o0[k], W0[(size_t)k * OD + t], acc);
        o0[b * OD + t] = sigmoidf_(acc);
    }
}

// ---------------- o1 ----------------
#define O1R 4
template <int D0, int D1, int D2>
__global__ void k_o1(const float* __restrict__ f0, const float* __restrict__ f1,
                     const float* __restrict__ r2, const float* __restrict__ W,
                     const float* __restrict__ bias, float* __restrict__ out) {
    constexpr int fan = D0 + D1 + 2 * D2;
    __shared__ float sg[O1R][fan];
    int row0 = blockIdx.x * O1R;
    int t = threadIdx.x;
    for (int idx = t; idx < O1R * fan; idx += OD) {
        int r = idx / fan, k = idx % fan;
        int row = row0 + r;
        int b = row / NN;
        float v;
        if (k < D0) v = f0[b * D0 + k];
        else if (k < D0 + D1) v = f1[(size_t)row * D1 + (k - D0)];
        else v = r2[(size_t)row * 2 * D2 + (k - D0 - D1)];
        sg[r][k] = v;
    }
    __syncthreads();
    float acc[O1R];
#pragma unroll
    for (int r = 0; r < O1R; r++) acc[r] = bias[t];
#pragma unroll 8
    for (int k = 0; k < fan; k++) {
        float w = W[(size_t)k * OD + t];
#pragma unroll
        for (int r = 0; r < O1R; r++) acc[r] = fmaf(sg[r][k], w, acc[r]);
    }
#pragma unroll
    for (int r = 0; r < O1R; r++)
        out[(size_t)(row0 + r) * OD + t] = sigmoidf_(acc[r]);
}

// ---------------- o2: mma.sync fp16 + ldmatrix + fused j-reduction ----------
#define AST 20
#define BST 20
#define ABUF (128 * AST)
#define BBUF (128 * BST)
#define O2_SMEM ((2 * ABUF + 2 * BBUF) * 4)

template <int D2, bool INH, bool OUTH, bool RED>
__global__ void __launch_bounds__(256, 2) k_o2m(
    const void* __restrict__ f2v, const float* __restrict__ Q,
    const float* __restrict__ P, const __half* __restrict__ Wt,
    const float* __restrict__ bias, void* __restrict__ outv,
    float* __restrict__ r2n) {
    constexpr int K = 2 * D2;
    constexpr int NS = K / 32;

    extern __shared__ uint32_t smw[];
    uint32_t* Ab = smw;
    uint32_t base_u32 = smem_to_u32(smw);
    uint32_t sb_addr = base_u32 + 2 * ABUF * 4;

    int tx = threadIdx.x;
    int lane = tx & 31, warp = tx >> 5;
    int warpM = warp & 1, warpN = warp >> 1;
    int gi = lane >> 2, ci = lane & 3;
    int b = blockIdx.z, i = blockIdx.y, j0 = blockIdx.x * 128;
    size_t bi = ((size_t)(b * NN + i)) * NN;

    int aRow16 = ((lane >> 3) & 1) * 8 + (lane & 7);
    int aKw = (lane >> 4) * 4;
    int bRow = ((lane >> 4) & 1) * 8 + (lane & 7);
    int bKw = ((lane >> 3) & 1) * 4;

    float acc[4][4][4];
#pragma unroll
    for (int mt = 0; mt < 4; mt++)
#pragma unroll
        for (int nt = 0; nt < 4; nt++)
#pragma unroll
            for (int v = 0; v < 4; v++) acc[mt][nt][v] = 0.0f;

    auto doMMA = [&](int p) {
        uint32_t aStage = base_u32 + (uint32_t)(p * ABUF) * 4;
        uint32_t bStage = base_u32 + (uint32_t)((2 * ABUF) + p * BBUF) * 4;
#pragma unroll
        for (int ks = 0; ks < 2; ks++) {
            uint32_t af[4][4];
#pragma unroll
            for (int mt = 0; mt < 4; mt++) {
                uint32_t addr = aStage + (uint32_t)((warpM * 64 + aRow16) * AST + aKw + mt * 16 * AST + ks * 8) * 4u;
                ldm_x4(af[mt][0], af[mt][1], af[mt][2], af[mt][3], addr);
            }
            uint32_t bf[4][2];
#pragma unroll
            for (int h = 0; h < 2; h++) {
                uint32_t addr = bStage + (uint32_t)((warpN * 32 + bRow) * BST + bKw + h * 16 * BST + ks * 8) * 4u;
                ldm_x4(bf[2 * h][0], bf[2 * h][1], bf[2 * h + 1][0], bf[2 * h + 1][1], addr);
            }
#pragma unroll
            for (int mt = 0; mt < 4; mt++)
#pragma unroll
                for (int nt = 0; nt < 4; nt++)
                    mma_f16(acc[mt][nt], af[mt], bf[nt]);
        }
    };

    auto fillB = [&](int p, int c0) {
#pragma unroll
        for (int it = 0; it < 2; it++) {
            int t = tx + it * 256;
            int row = t >> 2, chunk = t & 3;
            uint32_t dst = sb_addr + (uint32_t)(p * BBUF + row * BST + chunk * 4) * 4u;
            CP_ASYNC16(dst, Wt + (size_t)row * K + c0 + chunk * 8);
        }
    };

    if constexpr (INH) {
        const __half* f2h = (const __half*)f2v;
        const __half* hH1[2];
        const __half* hH2[2];
#pragma unroll
        for (int it = 0; it < 2; it++) {
            int rowj = j0 + (tx >> 2) + it * 64;
            hH1[it] = f2h + (bi + rowj) * D2;
            hH2[it] = f2h + (((size_t)(b * NN + rowj)) * NN + i) * D2 - D2;
        }
        int cc = (tx & 3) * 8;
        auto fillA = [&](int p, int c0) {
#pragma unroll
            for (int it = 0; it < 2; it++) {
                int row = (tx >> 2) + it * 64;
                const __half* src = ((c0 < D2) ? hH1[it] : hH2[it]) + c0 + cc;
                uint32_t dst = base_u32 + (uint32_t)(p * ABUF + row * AST + (tx & 3) * 4) * 4u;
                CP_ASYNC16(dst, src);
            }
        };
        fillA(0, 0);
        fillB(0, 0);
        CP_COMMIT();
        for (int s = 0; s < NS; s++) {
            int p = s & 1;
            if (s + 1 < NS) {
                fillA(p ^ 1, (s + 1) * 32);
                fillB(p ^ 1, (s + 1) * 32);
                CP_COMMIT();
                CP_WAIT(1);
            } else {
                CP_WAIT(0);
            }
            __syncthreads();
            doMMA(p);
            __syncthreads();
        }
    } else {
        const float* f2 = (const float*)f2v;
        const float* aH1[4];
        const float* aH2[4];
#pragma unroll
        for (int it = 0; it < 4; it++) {
            int rowj = j0 + ((tx + it * 256) >> 3);
            aH1[it] = f2 + (bi + rowj) * D2;
            aH2[it] = f2 + (((size_t)(b * NN + rowj)) * NN + i) * D2 - D2;
        }
        fillB(0, 0);
        CP_COMMIT();
        float4 ra[4];
#pragma unroll
        for (int it = 0; it < 4; it++) {
            int q = (tx + it * 256) & 7;
            ra[it] = *(const float4*)(aH1[it] + q * 4);
        }
        for (int s = 0; s < NS; s++) {
            int p = s & 1;
#pragma unroll
            for (int it = 0; it < 4; it++) {
                int t = tx + it * 256;
                int row = t >> 3, q = t & 7;
                uint2 v;
                v.x = pack_f16x2(ra[it].x, ra[it].y);
                v.y = pack_f16x2(ra[it].z, ra[it].w);
                *(uint2*)(Ab + p * ABUF + row * AST + q * 2) = v;
            }
            __syncthreads();
            if (s + 1 < NS) {
                fillB(p ^ 1, (s + 1) * 32);
                CP_COMMIT();
                CP_WAIT(1);
            } else {
                CP_WAIT(0);
            }
            __syncthreads();
            if (s + 1 < NS) {
                int c0n = (s + 1) * 32;
#pragma unroll
                for (int it = 0; it < 4; it++) {
                    int q = (tx + it * 256) & 7;
                    const float* basep = (c0n < D2) ? aH1[it] : aH2[it];
                    ra[it] = *(const float4*)(basep + c0n + q * 4);
                }
            }
            doMMA(p);
        }
    }

    // ---- epilogue (+ optional fused j-reduction into next layer's r2) ----
    __syncthreads();
    float* sQB = (float*)smw;
    uint32_t* smx = smw + 128;
    uint32_t* smn = smw + 256;
    if (tx < 128) {
        sQB[tx] = Q[((size_t)(b * NN + i)) * OD + tx] + bias[tx];
        if constexpr (RED) {
            smx[tx] = 0u;
            smn[tx] = 0x3F800000u;  // 1.0f
        }
    }
    __syncthreads();
    float lmx[8], lmn[8];
    if constexpr (RED) {
#pragma unroll
        for (int c = 0; c < 8; c++) { lmx[c] = 0.0f; lmn[c] = 1.0f; }
    }
#pragma unroll
    for (int mt = 0; mt < 4; mt++) {
#pragma unroll
        for (int rr = 0; rr < 2; rr++) {
            int j = j0 + warpM * 64 + mt * 16 + gi + rr * 8;
            const float* pRow = P + ((size_t)(b * NN + j)) * OD;
#pragma unroll
            for (int nt = 0; nt < 4; nt++) {
                int col = warpN * 32 + nt * 8 + ci * 2;
                float2 p2 = *(const float2*)(pRow + col);
                float ox = sigmoidf_(acc[mt][nt][rr * 2 + 0] + sQB[col + 0] + p2.x);
                float oy = sigmoidf_(acc[mt][nt][rr * 2 + 1] + sQB[col + 1] + p2.y);
                if constexpr (RED) {
                    if (j != i) {
                        int c = nt * 2;
                        lmx[c] = fmaxf(lmx[c], ox);
                        lmn[c] = fminf(lmn[c], ox);
                        lmx[c + 1] = fmaxf(lmx[c + 1], oy);
                        lmn[c + 1] = fminf(lmn[c + 1], oy);
                    }
                }
                if constexpr (OUTH) {
                    __half* oRow = (__half*)outv + (bi + j) * OD;
                    *(uint32_t*)(oRow + col) = pack_f16x2(ox, oy);
                } else {
                    float* oRow = (float*)outv + (bi + j) * OD;
                    float2 o;
                    o.x = ox; o.y = oy;
                    *(float2*)(oRow + col) = o;
                }
            }
        }
    }
    if constexpr (RED) {
        // positive floats: uint-bit order == float order
#pragma unroll
        for (int c = 0; c < 8; c++) {
            int col = warpN * 32 + (c >> 1) * 8 + ci * 2 + (c & 1);
            atomicMax(&smx[col], __float_as_uint(lmx[c]));
            atomicMin(&smn[col], __float_as_uint(lmn[c]));
        }
        __syncthreads();
        if (tx < 128) {
            size_t rowbase = ((size_t)(b * NN + i)) * (2 * OD);
            atomicMax((unsigned int*)r2n + rowbase + tx, smx[tx]);
            atomicMin((unsigned int*)r2n + rowbase + OD + tx, smn[tx]);
        }
    }
}

// ---------------- host side ----------------
template <int D0, int D1, int D2, typename T2, bool OUTH, bool RED, bool DORED>
static void run_layer(const float* f0, const float* f1, const T2* f2,
                      const float* W0, const float* b0,
                      const float* W1, const float* b1,
                      const float* W2, const float* b2,
                      float* o0, float* o1, void* o2,
                      float* r2, float* r2n, float* Q, float* P, __half* Wt) {
    constexpr bool INH = (sizeof(T2) == 2);
    cudaFuncSetAttribute(k_o2m<D2, INH, OUTH, RED>,
                         cudaFuncAttributeMaxDynamicSharedMemorySize, O2_SMEM);
    int grid = (DORED ? 1024 : 0) + 1024 + 2 * D2 + NB;
    k_prep<D0, D1, D2, T2, DORED><<<grid, 128>>>(f0, f1, f2, W0, b0, W2,
                                                 r2, Q, P, Wt, o0, r2n);
    k_o1<D0, D1, D2><<<NB * NN / O1R, OD>>>(f0, f1, r2, W1, b1, o1);
    k_o2m<D2, INH, OUTH, RED><<<dim3(NN / 128, NN, NB), 256, O2_SMEM>>>(
        f2, Q, P, Wt, b2, o2, r2n);
}

extern "C" void kernel_launch(void* const* d_in, const int* in_sizes, int n_in,
                              void* d_out, int out_size) {
    const float* x0 = (const float*)d_in[0];
    const float* x1 = (const float*)d_in[1];
    const float* x2 = (const float*)d_in[2];
    const float* W[3][3];
    const float* Bv[3][3];
    for (int l = 0; l < 3; l++)
        for (int o = 0; o < 3; o++) {
            W[l][o] = (const float*)d_in[3 + l * 6 + o * 2];
            Bv[l][o] = (const float*)d_in[3 + l * 6 + o * 2 + 1];
        }

    float *f0a, *f0b, *f1a, *f1b, *r2A, *r2B, *Q, *P;
    __half *h2a, *h2b, *Wt;
    cudaGetSymbolAddress((void**)&f0a, g_f0a);
    cudaGetSymbolAddress((void**)&f0b, g_f0b);
    cudaGetSymbolAddress((void**)&f1a, g_f1a);
    cudaGetSymbolAddress((void**)&f1b, g_f1b);
    cudaGetSymbolAddress((void**)&h2a, g_h2a);
    cudaGetSymbolAddress((void**)&h2b, g_h2b);
    cudaGetSymbolAddress((void**)&r2A, g_r2A);
    cudaGetSymbolAddress((void**)&r2B, g_r2B);
    cudaGetSymbolAddress((void**)&Q, g_Q);
    cudaGetSymbolAddress((void**)&P, g_P);
    cudaGetSymbolAddress((void**)&Wt, g_Wt);

    float* out = (float*)d_out;
    float* out0 = out;
    float* out1 = out + NB * OD;
    float* out2 = out + NB * OD + (size_t)NB * NN * OD;

    // layer 0: fp32 in, fp16 out; reduce2 on x2 in prep; o2m reduces -> r2B
    run_layer<32, 64, 64, float, true, true, true>(
        x0, x1, x2, W[0][0], Bv[0][0], W[0][1], Bv[0][1], W[0][2], Bv[0][2],
        f0a, f1a, h2a, r2A, r2B, Q, P, Wt);
    // layer 1: fp16 in/out; r2 from o2m(0); o2m reduces -> r2A
    run_layer<128, 128, 128, __half, true, true, false>(
        f0a, f1a, h2a, W[1][0], Bv[1][0], W[1][1], Bv[1][1], W[1][2], Bv[1][2],
        f0b, f1b, h2b, r2B, r2A, Q, P, Wt);
    // layer 2: fp16 in, fp32 out; r2 from o2m(1); no reduction
    run_layer<128, 128, 128, __half, false, false, false>(
        f0b, f1b, h2b, W[2][0], Bv[2][0], W[2][1], Bv[2][1], W[2][2], Bv[2][2],
        out0, out1, out2, r2A, (float*)nullptr, Q, P, Wt);
}

// round 17
// speedup vs baseline: 1.1326x; 1.1326x over previous
#include <cuda_runtime.h>
#include <cuda_fp16.h>
#include <math.h>
#include <cstdint>

#define NB 4
#define NN 256
#define OD 128

// ---------------- scratch (device globals; no allocation) ----------------
__device__ float g_f0a[NB * OD];
__device__ float g_f0b[NB * OD];
__device__ float g_f1a[NB * NN * OD];
__device__ float g_f1b[NB * NN * OD];
__device__ __half g_h2a[(size_t)NB * NN * NN * OD];  // fp16 f2 intermediates
__device__ __half g_h2b[(size_t)NB * NN * NN * OD];
__device__ float g_r2[NB * NN * 2 * OD];
__device__ float g_Q[NB * NN * OD];
__device__ float g_P[NB * NN * OD];
__device__ __half g_Wt[OD * 2 * OD];  // n-major fp16: Wt[n][k]

__device__ __forceinline__ float sigmoidf_(float x) {
    return 1.0f / (1.0f + __expf(-x));
}
__device__ __forceinline__ uint32_t smem_to_u32(const void* p) {
    uint32_t a;
    asm("{ .reg .u64 t; cvta.to.shared.u64 t, %1; cvt.u32.u64 %0, t; }" : "=r"(a) : "l"(p));
    return a;
}
__device__ __forceinline__ uint32_t pack_f16x2(float x, float y) {
    uint32_t r;
    asm("cvt.rn.f16x2.f32 %0, %2, %1;" : "=r"(r) : "f"(x), "f"(y));
    return r;
}
#define CP_ASYNC16(dst, src) \
    asm volatile("cp.async.cg.shared.global [%0], [%1], 16;" :: "r"(dst), "l"(src) : "memory")
#define CP_COMMIT() asm volatile("cp.async.commit_group;" ::: "memory")
#define CP_WAIT(n) asm volatile("cp.async.wait_group %0;" :: "n"(n) : "memory")

__device__ __forceinline__ void mma_f16(float* d, const uint32_t* a, const uint32_t* b) {
    asm volatile(
        "mma.sync.aligned.m16n8k16.row.col.f32.f16.f16.f32 "
        "{%0,%1,%2,%3}, {%4,%5,%6,%7}, {%8,%9}, {%0,%1,%2,%3};"
        : "+f"(d[0]), "+f"(d[1]), "+f"(d[2]), "+f"(d[3])
        : "r"(a[0]), "r"(a[1]), "r"(a[2]), "r"(a[3]), "r"(b[0]), "r"(b[1]));
}
__device__ __forceinline__ void ldm_x4(uint32_t& r0, uint32_t& r1, uint32_t& r2,
                                       uint32_t& r3, uint32_t addr) {
    asm volatile("ldmatrix.sync.aligned.m8n8.x4.shared.b16 {%0,%1,%2,%3}, [%4];"
                 : "=r"(r0), "=r"(r1), "=r"(r2), "=r"(r3) : "r"(addr));
}

// ---------------- fused prep: reduce2 | qp | wt | o0 ------------------------
template <int D0, int D1, int D2, typename T2>
__global__ void k_prep(const float* __restrict__ f0, const float* __restrict__ f1,
                       const T2* __restrict__ f2, const float* __restrict__ W0,
                       const float* __restrict__ b0, const float* __restrict__ W2,
                       float* __restrict__ r2, float* __restrict__ Q,
                       float* __restrict__ P, __half* __restrict__ Wt,
                       float* __restrict__ o0) {
    constexpr int K = 2 * D2;
    int blk = blockIdx.x, t = threadIdx.x;
    __shared__ float s_qp[OD];
    __shared__ float s_o0[3 * OD];
    __shared__ __half2 sredx[8][16][4];
    __shared__ __half2 sredn[8][16][4];
    if (blk < 1024) {
        int i = blk & 255, b = blk >> 8;
        size_t rowbase = ((size_t)(b * NN + i)) * K;
        if constexpr (sizeof(T2) == 2) {
            // fp16 vectorized: 16 lanes x 8 halves cover D2=128; 8 j-groups
            int lc = t & 15, jg = t >> 4;
            const __half2 zero2 = __floats2half2_rn(0.0f, 0.0f);
            const __half2 one2 = __floats2half2_rn(1.0f, 1.0f);
            __half2 mx[4], mn[4];
#pragma unroll
            for (int q = 0; q < 4; q++) { mx[q] = zero2; mn[q] = one2; }
            const __half* base = (const __half*)f2 +
                                 ((size_t)(b * NN + i)) * NN * D2 + lc * 8;
#pragma unroll 4
            for (int j = jg; j < NN; j += 8) {
                uint4 raw = *(const uint4*)(base + (size_t)j * D2);
                __half2 v[4];
                v[0] = *(__half2*)&raw.x; v[1] = *(__half2*)&raw.y;
                v[2] = *(__half2*)&raw.z; v[3] = *(__half2*)&raw.w;
                bool diag = (j == i);
#pragma unroll
                for (int q = 0; q < 4; q++) {
                    mx[q] = __hmax2(mx[q], diag ? zero2 : v[q]);
                    mn[q] = __hmin2(mn[q], diag ? one2 : v[q]);
                }
            }
#pragma unroll
            for (int q = 0; q < 4; q++) { sredx[jg][lc][q] = mx[q]; sredn[jg][lc][q] = mn[q]; }
            __syncthreads();
            if (t < 16) {
#pragma unroll
                for (int q = 0; q < 4; q++) { mx[q] = sredx[0][t][q]; mn[q] = sredn[0][t][q]; }
#pragma unroll
                for (int g = 1; g < 8; g++)
#pragma unroll
                    for (int q = 0; q < 4; q++) {
                        mx[q] = __hmax2(mx[q], sredx[g][t][q]);
                        mn[q] = __hmin2(mn[q], sredn[g][t][q]);
                    }
#pragma unroll
                for (int q = 0; q < 4; q++) {
                    float2 fx = __half22float2(mx[q]);
                    float2 fn = __half22float2(mn[q]);
                    int d = t * 8 + q * 2;
                    r2[rowbase + d] = fx.x;
                    r2[rowbase + d + 1] = fx.y;
                    r2[rowbase + D2 + d] = fn.x;
                    r2[rowbase + D2 + d + 1] = fn.y;
                }
            }
        } else {
            if (t < D2) {
                const float* base = (const float*)f2 +
                                    ((size_t)(b * NN + i)) * NN * D2 + t;
                float mx = -1e30f, mn = 1e30f;
#pragma unroll 8
                for (int j = 0; j < NN; j++) {
                    float v = base[(size_t)j * D2];
                    mx = fmaxf(mx, (j == i) ? 0.0f : v);
                    mn = fminf(mn, (j == i) ? 1.0f : v);
                }
                r2[rowbase + t] = mx;
                r2[rowbase + D2 + t] = mn;
            }
        }
    } else if (blk < 2048) {
        int row = blk - 1024;
        if (t < D1) s_qp[t] = f1[(size_t)row * D1 + t];
        __syncthreads();
        const float* Wa = W2;
        const float* Wc = W2 + (size_t)(D1 + D2) * OD;
        float aq = 0.0f, ap = 0.0f;
#pragma unroll 8
        for (int k = 0; k < D1; k++) {
            float v = s_qp[k];
            aq = fmaf(v, Wa[(size_t)k * OD + t], aq);
            ap = fmaf(v, Wc[(size_t)k * OD + t], ap);
        }
        Q[(size_t)row * OD + t] = aq;
        P[(size_t)row * OD + t] = ap;
    } else if (blk < 2048 + K) {
        int k = blk - 2048;
        const float* src = (k < D2) ? W2 + (size_t)(D1 + k) * OD
                                    : W2 + (size_t)(2 * D1 + D2 + (k - D2)) * OD;
        Wt[(size_t)t * K + k] = __float2half_rn(src[t]);
    } else {
        int b = blk - (2048 + K);
        if (t < D0) s_o0[t] = f0[b * D0 + t];
        if (t < D1) {
            float mx = -1e30f, mn = 1e30f;
            const float* base = f1 + (size_t)b * NN * D1 + t;
#pragma unroll 8
            for (int i2 = 0; i2 < NN; i2++) {
                float v = base[(size_t)i2 * D1];
                mx = fmaxf(mx, v);
                mn = fminf(mn, v);
            }
            s_o0[D0 + t] = mx;
            s_o0[D0 + D1 + t] = mn;
        }
        __syncthreads();
        constexpr int fan = D0 + 2 * D1;
        float acc = b0[t];
#pragma unroll 8
        for (int k = 0; k < fan; k++) acc = fmaf(s_o0[k], W0[(size_t)k * OD + t], acc);
        o0[b * OD + t] = sigmoidf_(acc);
    }
}

// ---------------- o1: split-K (2 halves) x O1R rows -------------------------
#define O1R 4
template <int D0, int D1, int D2>
__global__ void __launch_bounds__(256) k_o1(
    const float* __restrict__ f0, const float* __restrict__ f1,
    const float* __restrict__ r2, const float* __restrict__ W,
    const float* __restrict__ bias, float* __restrict__ out) {
    constexpr int fan = D0 + D1 + 2 * D2;
    constexpr int H = fan / 2;
    __shared__ float sg[O1R][fan];
    __shared__ float part[O1R][OD];
    int row0 = blockIdx.x * O1R;
    int t = threadIdx.x;
    for (int idx = t; idx < O1R * fan; idx += 256) {
        int r = idx / fan, k = idx % fan;
        int row = row0 + r;
        int b = row / NN;
        float v;
        if (k < D0) v = f0[b * D0 + k];
        else if (k < D0 + D1) v = f1[(size_t)row * D1 + (k - D0)];
        else v = r2[(size_t)row * 2 * D2 + (k - D0 - D1)];
        sg[r][k] = v;
    }
    __syncthreads();
    int col = t & 127, hf = t >> 7;  // 2 K-halves
    float acc[O1R];
#pragma unroll
    for (int r = 0; r < O1R; r++) acc[r] = hf ? 0.0f : bias[col];
    const float* Wp = W + (size_t)(hf * H) * OD + col;
#pragma unroll 8
    for (int k = 0; k < H; k++) {
        float w = Wp[(size_t)k * OD];
#pragma unroll
        for (int r = 0; r < O1R; r++) acc[r] = fmaf(sg[r][hf * H + k], w, acc[r]);
    }
    if (hf) {
#pragma unroll
        for (int r = 0; r < O1R; r++) part[r][col] = acc[r];
    }
    __syncthreads();
    if (!hf) {
#pragma unroll
        for (int r = 0; r < O1R; r++)
            out[(size_t)(row0 + r) * OD + col] = sigmoidf_(acc[r] + part[r][col]);
    }
}

// ---------------- o2: mma.sync fp16 + ldmatrix ------------------------------
#define AST 20
#define BST 20
#define ABUF (128 * AST)
#define BBUF (128 * BST)
#define O2_SMEM ((2 * ABUF + 2 * BBUF) * 4)

template <int D2, bool INH, bool OUTH>
__global__ void __launch_bounds__(256, 2) k_o2m(
    const void* __restrict__ f2v, const float* __restrict__ Q,
    const float* __restrict__ P, const __half* __restrict__ Wt,
    const float* __restrict__ bias, void* __restrict__ outv) {
    constexpr int K = 2 * D2;
    constexpr int NS = K / 32;

    extern __shared__ uint32_t smw[];
    uint32_t* Ab = smw;
    uint32_t base_u32 = smem_to_u32(smw);
    uint32_t sb_addr = base_u32 + 2 * ABUF * 4;

    int tx = threadIdx.x;
    int lane = tx & 31, warp = tx >> 5;
    int warpM = warp & 1, warpN = warp >> 1;
    int gi = lane >> 2, ci = lane & 3;
    int b = blockIdx.z, i = blockIdx.y, j0 = blockIdx.x * 128;
    size_t bi = ((size_t)(b * NN + i)) * NN;

    int aRow16 = ((lane >> 3) & 1) * 8 + (lane & 7);
    int aKw = (lane >> 4) * 4;
    int bRow = ((lane >> 4) & 1) * 8 + (lane & 7);
    int bKw = ((lane >> 3) & 1) * 4;

    float acc[4][4][4];
#pragma unroll
    for (int mt = 0; mt < 4; mt++)
#pragma unroll
        for (int nt = 0; nt < 4; nt++)
#pragma unroll
            for (int v = 0; v < 4; v++) acc[mt][nt][v] = 0.0f;

    auto doMMA = [&](int p) {
        uint32_t aStage = base_u32 + (uint32_t)(p * ABUF) * 4;
        uint32_t bStage = base_u32 + (uint32_t)((2 * ABUF) + p * BBUF) * 4;
#pragma unroll
        for (int ks = 0; ks < 2; ks++) {
            uint32_t af[4][4];
#pragma unroll
            for (int mt = 0; mt < 4; mt++) {
                uint32_t addr = aStage + (uint32_t)((warpM * 64 + aRow16) * AST + aKw + mt * 16 * AST + ks * 8) * 4u;
                ldm_x4(af[mt][0], af[mt][1], af[mt][2], af[mt][3], addr);
            }
            uint32_t bf[4][2];
#pragma unroll
            for (int h = 0; h < 2; h++) {
                uint32_t addr = bStage + (uint32_t)((warpN * 32 + bRow) * BST + bKw + h * 16 * BST + ks * 8) * 4u;
                ldm_x4(bf[2 * h][0], bf[2 * h][1], bf[2 * h + 1][0], bf[2 * h + 1][1], addr);
            }
#pragma unroll
            for (int mt = 0; mt < 4; mt++)
#pragma unroll
                for (int nt = 0; nt < 4; nt++)
                    mma_f16(acc[mt][nt], af[mt], bf[nt]);
        }
    };

    auto fillB = [&](int p, int c0) {
#pragma unroll
        for (int it = 0; it < 2; it++) {
            int t = tx + it * 256;
            int row = t >> 2, chunk = t & 3;
            uint32_t dst = sb_addr + (uint32_t)(p * BBUF + row * BST + chunk * 4) * 4u;
            CP_ASYNC16(dst, Wt + (size_t)row * K + c0 + chunk * 8);
        }
    };

    if constexpr (INH) {
        const __half* f2h = (const __half*)f2v;
        const __half* hH1[2];
        const __half* hH2[2];
#pragma unroll
        for (int it = 0; it < 2; it++) {
            int rowj = j0 + (tx >> 2) + it * 64;
            hH1[it] = f2h + (bi + rowj) * D2;
            hH2[it] = f2h + (((size_t)(b * NN + rowj)) * NN + i) * D2 - D2;
        }
        int cc = (tx & 3) * 8;
        auto fillA = [&](int p, int c0) {
#pragma unroll
            for (int it = 0; it < 2; it++) {
                int row = (tx >> 2) + it * 64;
                const __half* src = ((c0 < D2) ? hH1[it] : hH2[it]) + c0 + cc;
                uint32_t dst = base_u32 + (uint32_t)(p * ABUF + row * AST + (tx & 3) * 4) * 4u;
                CP_ASYNC16(dst, src);
            }
        };
        fillA(0, 0);
        fillB(0, 0);
        CP_COMMIT();
        for (int s = 0; s < NS; s++) {
            int p = s & 1;
            if (s + 1 < NS) {
                fillA(p ^ 1, (s + 1) * 32);
                fillB(p ^ 1, (s + 1) * 32);
                CP_COMMIT();
                CP_WAIT(1);
            } else {
                CP_WAIT(0);
            }
            __syncthreads();
            doMMA(p);
            __syncthreads();
        }
    } else {
        const float* f2 = (const float*)f2v;
        const float* aH1[4];
        const float* aH2[4];
#pragma unroll
        for (int it = 0; it < 4; it++) {
            int rowj = j0 + ((tx + it * 256) >> 3);
            aH1[it] = f2 + (bi + rowj) * D2;
            aH2[it] = f2 + (((size_t)(b * NN + rowj)) * NN + i) * D2 - D2;
        }
        fillB(0, 0);
        CP_COMMIT();
        float4 ra[4];
#pragma unroll
        for (int it = 0; it < 4; it++) {
            int q = (tx + it * 256) & 7;
            ra[it] = *(const float4*)(aH1[it] + q * 4);
        }
        for (int s = 0; s < NS; s++) {
            int p = s & 1;
#pragma unroll
            for (int it = 0; it < 4; it++) {
                int t = tx + it * 256;
                int row = t >> 3, q = t & 7;
                uint2 v;
                v.x = pack_f16x2(ra[it].x, ra[it].y);
                v.y = pack_f16x2(ra[it].z, ra[it].w);
                *(uint2*)(Ab + p * ABUF + row * AST + q * 2) = v;
            }
            __syncthreads();
            if (s + 1 < NS) {
                fillB(p ^ 1, (s + 1) * 32);
                CP_COMMIT();
                CP_WAIT(1);
            } else {
                CP_WAIT(0);
            }
            __syncthreads();
            if (s + 1 < NS) {
                int c0n = (s + 1) * 32;
#pragma unroll
                for (int it = 0; it < 4; it++) {
                    int q = (tx + it * 256) & 7;
                    const float* basep = (c0n < D2) ? aH1[it] : aH2[it];
                    ra[it] = *(const float4*)(basep + c0n + q * 4);
                }
            }
            doMMA(p);
        }
    }

    // epilogue
    __syncthreads();
    float* sQB = (float*)smw;
    if (tx < 128) sQB[tx] = Q[((size_t)(b * NN + i)) * OD + tx] + bias[tx];
    __syncthreads();
#pragma unroll
    for (int mt = 0; mt < 4; mt++) {
#pragma unroll
        for (int rr = 0; rr < 2; rr++) {
            int j = j0 + warpM * 64 + mt * 16 + gi + rr * 8;
            const float* pRow = P + ((size_t)(b * NN + j)) * OD;
#pragma unroll
            for (int nt = 0; nt < 4; nt++) {
                int col = warpN * 32 + nt * 8 + ci * 2;
                float2 p2 = *(const float2*)(pRow + col);
                float ox = sigmoidf_(acc[mt][nt][rr * 2 + 0] + sQB[col + 0] + p2.x);
                float oy = sigmoidf_(acc[mt][nt][rr * 2 + 1] + sQB[col + 1] + p2.y);
                if constexpr (OUTH) {
                    __half* oRow = (__half*)outv + (bi + j) * OD;
                    *(uint32_t*)(oRow + col) = pack_f16x2(ox, oy);
                } else {
                    float* oRow = (float*)outv + (bi + j) * OD;
                    float2 o;
                    o.x = ox; o.y = oy;
                    *(float2*)(oRow + col) = o;
                }
            }
        }
    }
}

// ---------------- host side ----------------
template <int D0, int D1, int D2, typename T2, bool OUTH>
static void run_layer(const float* f0, const float* f1, const T2* f2,
                      const float* W0, const float* b0,
                      const float* W1, const float* b1,
                      const float* W2, const float* b2,
                      float* o0, float* o1, void* o2,
                      float* r2, float* Q, float* P, __half* Wt) {
    constexpr bool INH = (sizeof(T2) == 2);
    cudaFuncSetAttribute(k_o2m<D2, INH, OUTH>,
                         cudaFuncAttributeMaxDynamicSharedMemorySize, O2_SMEM);
    k_prep<D0, D1, D2, T2><<<2048 + 2 * D2 + NB, 128>>>(f0, f1, f2, W0, b0, W2,
                                                        r2, Q, P, Wt, o0);
    k_o1<D0, D1, D2><<<NB * NN / O1R, 256>>>(f0, f1, r2, W1, b1, o1);
    k_o2m<D2, INH, OUTH><<<dim3(NN / 128, NN, NB), 256, O2_SMEM>>>(
        f2, Q, P, Wt, b2, o2);
}

extern "C" void kernel_launch(void* const* d_in, const int* in_sizes, int n_in,
                              void* d_out, int out_size) {
    const float* x0 = (const float*)d_in[0];
    const float* x1 = (const float*)d_in[1];
    const float* x2 = (const float*)d_in[2];
    const float* W[3][3];
    const float* Bv[3][3];
    for (int l = 0; l < 3; l++)
        for (int o = 0; o < 3; o++) {
            W[l][o] = (const float*)d_in[3 + l * 6 + o * 2];
            Bv[l][o] = (const float*)d_in[3 + l * 6 + o * 2 + 1];
        }

    float *f0a, *f0b, *f1a, *f1b, *r2, *Q, *P;
    __half *h2a, *h2b, *Wt;
    cudaGetSymbolAddress((void**)&f0a, g_f0a);
    cudaGetSymbolAddress((void**)&f0b, g_f0b);
    cudaGetSymbolAddress((void**)&f1a, g_f1a);
    cudaGetSymbolAddress((void**)&f1b, g_f1b);
    cudaGetSymbolAddress((void**)&h2a, g_h2a);
    cudaGetSymbolAddress((void**)&h2b, g_h2b);
    cudaGetSymbolAddress((void**)&r2, g_r2);
    cudaGetSymbolAddress((void**)&Q, g_Q);
    cudaGetSymbolAddress((void**)&P, g_P);
    cudaGetSymbolAddress((void**)&Wt, g_Wt);

    float* out = (float*)d_out;
    float* out0 = out;
    float* out1 = out + NB * OD;
    float* out2 = out + NB * OD + (size_t)NB * NN * OD;

    // layer 0: fp32 in, fp16 out
    run_layer<32, 64, 64, float, true>(x0, x1, x2,
                                       W[0][0], Bv[0][0], W[0][1], Bv[0][1],
                                       W[0][2], Bv[0][2],
                                       f0a, f1a, h2a, r2, Q, P, Wt);
    // layer 1: fp16 in, fp16 out
    run_layer<128, 128, 128, __half, true>(f0a, f1a, h2a,
                                           W[1][0], Bv[1][0], W[1][1], Bv[1][1],
                                           W[1][2], Bv[1][2],
                                           f0b, f1b, h2b, r2, Q, P, Wt);
    // layer 2: fp16 in, fp32 out (to d_out)
    run_layer<128, 128, 128, __half, false>(f0b, f1b, h2b,
                                            W[2][0], Bv[2][0], W[2][1], Bv[2][1],
                                            W[2][2], Bv[2][2],
                                            out0, out1, out2, r2, Q, P, Wt);
}